// round 13
// baseline (speedup 1.0000x reference)
#include <cuda_runtime.h>
#include <cuda_bf16.h>

#define T 1024
#define D 1024
#define H 16
#define DHD 64
#define DFF 4096

// ---------------- static scratch (device globals; no allocation) ----------------
__device__ float g_hs[T * D];
__device__ float g_hbuf[T * D];
__device__ float g_q[T * D];
__device__ float g_k[T * D];
__device__ float g_v[T * D];
__device__ float g_beta[T * H];
__device__ float g_o[T * D];
__device__ float g_kc[T * D];
__device__ float g_vc[T * D];
__device__ float g_kcr[T * D];
__device__ float g_scores[(size_t)H * T * T];
__device__ float g_ff1[T * DFF];
__device__ float g_ff2[T * DFF];
__device__ float g_cos[T * 32];
__device__ float g_sin[T * 32];
__device__ uint2 g_asp[(size_t)H * T * T / 2];  // pre-split A (max: scores)
__device__ uint2 g_bsp[(size_t)D * DFF / 2];    // pre-split B (max: up/gate W)
__device__ uint2 g_ktp[32 * H * T];             // pre-split K^T pairs [32][H*T]
__device__ uint2 g_vcp[(T / 2) * D];            // pre-split vc pairs [T/2][D]
__device__ float g_wy_u[H * 16 * 64 * 64];      // WY: Utilde per (h,chunk)
__device__ float g_wy_w[H * 16 * 64 * 64];      // WY: W per (h,chunk)
__device__ float g_wy_aqk[H * 16 * 64 * 64];    // WY: tril(QK^T) per (h,chunk)

// ---------------- embedding gather ----------------
__global__ void embed_k(const int* __restrict__ ids, const float* __restrict__ emb,
                        float* __restrict__ out) {
    int t = blockIdx.x;
    int id = ids[t];
    for (int i = threadIdx.x; i < D; i += 256)
        out[(size_t)t * D + i] = emb[(size_t)id * D + i];
}

// ---------------- rope tables ----------------
__global__ void rope_tab_k(float* __restrict__ ct, float* __restrict__ st) {
    int t = blockIdx.x, i = threadIdx.x;  // i in [0,32)
    float inv = __powf(10000.0f, -(float)i / 32.0f);
    float f = (float)t * inv;
    ct[t * 32 + i] = cosf(f);
    st[t * 32 + i] = sinf(f);
}

// rope apply on [T, H, 64]; in may equal out
__global__ void rope_apply_k(const float* __restrict__ in, float* __restrict__ out,
                             const float* __restrict__ ct, const float* __restrict__ st) {
    int idx = blockIdx.x * 256 + threadIdx.x;  // T*H*32 total
    if (idx >= T * H * 32) return;
    int d = idx & 31;
    int th = idx >> 5;
    int h = th & (H - 1);
    int t = th >> 4;
    float c = ct[t * 32 + d], s = st[t * 32 + d];
    const float* pi = in + (size_t)t * D + h * DHD;
    float* po = out + (size_t)t * D + h * DHD;
    float x0 = pi[d], x1 = pi[d + 32];
    po[d] = x0 * c - x1 * s;
    po[d + 32] = x1 * c + x0 * s;
}

// ---------------- bf16 RN split: pair (x0,x1) -> (hi bf16x2 [low=x0], lo bf16x2) ------------
__device__ __forceinline__ uint2 bfsplit2_rn(float x0, float x1) {
    unsigned hi;
    asm("cvt.rn.bf16x2.f32 %0, %1, %2;" : "=r"(hi) : "f"(x1), "f"(x0));
    float h0 = __uint_as_float(hi << 16);
    float h1 = __uint_as_float(hi & 0xFFFF0000u);
    unsigned lo;
    asm("cvt.rn.bf16x2.f32 %0, %1, %2;" : "=r"(lo) : "f"(x1 - h1), "f"(x0 - h0));
    return make_uint2(hi, lo);
}

// A-style pre-split: row-major [M][K], adjacent-k pairs. npairs = M*K/2.
__global__ void presplitA_k(const float* __restrict__ in, uint2* __restrict__ out, int npairs) {
    int i = blockIdx.x * 256 + threadIdx.x;
    if (i >= npairs) return;
    float2 v = ((const float2*)in)[i];
    out[i] = bfsplit2_rn(v.x, v.y);
}

// B-style pre-split: [K][N] row-major, pairs rows (2p, 2p+1). out[p*N + n].
__global__ void presplitB_k(const float* __restrict__ in, uint2* __restrict__ out,
                            int Kd, int Nd) {
    int i = blockIdx.x * 256 + threadIdx.x;
    if (i >= (Kd / 2) * Nd) return;
    int n = i % Nd, p = i / Nd;
    out[i] = bfsplit2_rn(in[(size_t)(2 * p) * Nd + n], in[(size_t)(2 * p + 1) * Nd + n]);
}

// fused A-split + B-split in one launch
__global__ void presplitAB_k(const float* __restrict__ inA, uint2* __restrict__ outA, int npA,
                             const float* __restrict__ inB, uint2* __restrict__ outB,
                             int Kb, int Nb) {
    int i = blockIdx.x * 256 + threadIdx.x;
    if (i < npA) {
        float2 v = ((const float2*)inA)[i];
        outA[i] = bfsplit2_rn(v.x, v.y);
    } else {
        int j = i - npA;
        if (j < (Kb / 2) * Nb) {
            int n = j % Nb, p = j / Nb;
            outB[j] = bfsplit2_rn(inB[(size_t)(2 * p) * Nb + n],
                                  inB[(size_t)(2 * p + 1) * Nb + n]);
        }
    }
}

// K^T pre-split: kcr [T][H*64] -> out[p][h*T + s]
__global__ void presplitKT_k(const float* __restrict__ in, uint2* __restrict__ out) {
    int h = blockIdx.y;
    int s0 = blockIdx.x * 32;
    __shared__ float sm[32][65];
    int tid = threadIdx.x;
    for (int idx = tid; idx < 32 * 64; idx += 256) {
        int rr = idx >> 6, cc = idx & 63;
        sm[rr][cc] = in[(size_t)(s0 + rr) * D + h * 64 + cc];
    }
    __syncthreads();
    for (int idx = tid; idx < 1024; idx += 256) {
        int p = idx >> 5, sp = idx & 31;
        out[(size_t)p * (H * T) + h * T + s0 + sp] = bfsplit2_rn(sm[sp][2 * p], sm[sp][2 * p + 1]);
    }
}

__device__ __forceinline__ void mma_bf16(float* d, unsigned a0, unsigned a1, unsigned a2,
                                         unsigned a3, unsigned b0, unsigned b1) {
    asm volatile(
        "mma.sync.aligned.m16n8k16.row.col.f32.bf16.bf16.f32 "
        "{%0,%1,%2,%3}, {%4,%5,%6,%7}, {%8,%9}, {%0,%1,%2,%3};"
        : "+f"(d[0]), "+f"(d[1]), "+f"(d[2]), "+f"(d[3])
        : "r"(a0), "r"(a1), "r"(a2), "r"(a3), "r"(b0), "r"(b1));
}

// ---------------- tensor-core GEMM (3xBF16, operands pre-split in global) ----------------
__global__ __launch_bounds__(256) void tcgemm_k(
        const uint2* __restrict__ A, const uint2* __restrict__ B,
        const float* __restrict__ bias, const float* __restrict__ mulb,
        const float* __restrict__ resb, float* __restrict__ C,
        int M, int N, int Kp, int ldap, int ldb, int ldc,
        long sAp, long sBp, long sC, int act, int kbound) {
    int bz = blockIdx.z;
    A += (long)bz * sAp;
    B += (long)bz * sBp;
    C += (long)bz * sC;
    const float* mulp = mulb ? mulb + (long)bz * sC : nullptr;
    const float* resp = resb ? resb + (long)bz * sC : nullptr;

    int bm = blockIdx.y * 64, bn = blockIdx.x * 64;

    int tid = threadIdx.x;
    int lane = tid & 31;
    int warp = tid >> 5;
    int wm = warp >> 2;
    int wn = warp & 3;
    int grp = lane >> 2;
    int tig = lane & 3;

    if (act == 3 && bn >= bm + 64) {
#pragma unroll
        for (int mt = 0; mt < 2; mt++)
#pragma unroll
            for (int nt = 0; nt < 2; nt++)
#pragma unroll
                for (int r = 0; r < 4; r++) {
                    int gm = bm + wm * 32 + mt * 16 + grp + (r >> 1) * 8;
                    int gn = bn + wn * 16 + nt * 8 + tig * 2 + (r & 1);
                    C[(long)gm * ldc + gn] = -1e30f;
                }
        return;
    }

    if (kbound) {
        int lim = (bm + 64) / 2;
        if (lim < Kp) Kp = lim;
    }

    __shared__ uint2 Asp[64][12];
    __shared__ uint2 Bsp[64][12];

    int arow = tid >> 2;
    int atig = tid & 3;
    int bkp = lane >> 2;
    int bn0 = warp * 8 + (lane & 3);

    uint2 aU0, aU1, bU0, bU1;
    auto gload = [&](int kp0) {
        const uint2* ap = A + (long)(bm + arow) * ldap + kp0;
        aU0 = ap[atig];
        aU1 = ap[atig + 4];
        const uint2* bp = B + (long)(kp0 + bkp) * ldb + bn;
        bU0 = bp[bn0];
        bU1 = bp[bn0 + 4];
    };
    auto sstore = [&]() {
        Asp[arow][atig] = aU0;
        Asp[arow][atig + 4] = aU1;
        Bsp[bn0][bkp] = bU0;
        Bsp[bn0 + 4][bkp] = bU1;
    };

    float acc[2][2][4];
#pragma unroll
    for (int i = 0; i < 2; i++)
#pragma unroll
        for (int j = 0; j < 2; j++)
#pragma unroll
            for (int r = 0; r < 4; r++) acc[i][j][r] = 0.f;

    gload(0);
    sstore();
    __syncthreads();

    for (int kp0 = 0; kp0 < Kp; kp0 += 8) {
        bool more = (kp0 + 8) < Kp;
        if (more) gload(kp0 + 8);

        uint2 aE[2][4];
#pragma unroll
        for (int mt = 0; mt < 2; mt++) {
            int m = wm * 32 + mt * 16 + grp;
            aE[mt][0] = Asp[m][tig];
            aE[mt][1] = Asp[m + 8][tig];
            aE[mt][2] = Asp[m][tig + 4];
            aE[mt][3] = Asp[m + 8][tig + 4];
        }
        uint2 bE[2][2];
#pragma unroll
        for (int nt = 0; nt < 2; nt++) {
            int n = wn * 16 + nt * 8 + grp;
            bE[nt][0] = Bsp[n][tig];
            bE[nt][1] = Bsp[n][tig + 4];
        }
#pragma unroll
        for (int mt = 0; mt < 2; mt++)
#pragma unroll
            for (int nt = 0; nt < 2; nt++) {
                float* d = acc[mt][nt];
                mma_bf16(d, aE[mt][0].x, aE[mt][1].x, aE[mt][2].x, aE[mt][3].x,
                         bE[nt][0].x, bE[nt][1].x);
                mma_bf16(d, aE[mt][0].y, aE[mt][1].y, aE[mt][2].y, aE[mt][3].y,
                         bE[nt][0].x, bE[nt][1].x);
                mma_bf16(d, aE[mt][0].x, aE[mt][1].x, aE[mt][2].x, aE[mt][3].x,
                         bE[nt][0].y, bE[nt][1].y);
            }
        __syncthreads();
        if (more) {
            sstore();
            __syncthreads();
        }
    }

#pragma unroll
    for (int mt = 0; mt < 2; mt++)
#pragma unroll
        for (int nt = 0; nt < 2; nt++)
#pragma unroll
            for (int r = 0; r < 4; r++) {
                int gm = bm + wm * 32 + mt * 16 + grp + (r >> 1) * 8;
                int gn = bn + wn * 16 + nt * 8 + tig * 2 + (r & 1);
                float v = acc[mt][nt][r];
                if (bias) v += bias[gn];
                if (act == 1) v = v / (1.f + __expf(-v));
                else if (act == 2) v = 1.f / (1.f + __expf(-v));
                else if (act == 3) v = (gn <= gm) ? v * 0.125f : -1e30f;
                if (mulp) v *= mulp[(long)gm * ldc + gn];
                if (resp) v += resp[(long)gm * ldc + gn];
                C[(long)gm * ldc + gn] = v;
            }
}

// ---------------- SIMT GEMM fallback (small N; float inputs) ----------------
__global__ void gemm_k(const float* __restrict__ A, const float* __restrict__ Bm,
                       const float* __restrict__ bias, const float* __restrict__ mulb,
                       const float* __restrict__ resb, float* __restrict__ C,
                       int M, int N, int K, int lda, int ldb, int ldc,
                       long sA, long sB, long sC, int act) {
    int bz = blockIdx.z;
    A += (long)bz * sA;
    Bm += (long)bz * sB;
    C += (long)bz * sC;
    const float* mulp = mulb ? mulb + (long)bz * sC : nullptr;
    const float* resp = resb ? resb + (long)bz * sC : nullptr;

    int bm = blockIdx.y * 64, bn = blockIdx.x * 64;
    __shared__ float As[16][68];
    __shared__ float Bs[16][68];
    int tid = threadIdx.x;
    int ty = tid >> 4, tx = tid & 15;
    int aRow = tid >> 2;
    int aColBase = (tid & 3) * 4;
    int bRow = tid >> 4;
    int bColBase = (tid & 15) * 4;

    float acc[4][4];
#pragma unroll
    for (int i = 0; i < 4; i++)
#pragma unroll
        for (int j = 0; j < 4; j++) acc[i][j] = 0.f;

    for (int k0 = 0; k0 < K; k0 += 16) {
#pragma unroll
        for (int i = 0; i < 4; i++) {
            int kk = aColBase + i;
            int gm = bm + aRow, gk = k0 + kk;
            float val = (gm < M) ? A[(long)gm * lda + gk] : 0.f;
            As[kk][aRow] = val;
        }
#pragma unroll
        for (int i = 0; i < 4; i++) {
            int nn = bColBase + i;
            int gn = bn + nn, gk = k0 + bRow;
            float val = (gn < N) ? Bm[(long)gk * ldb + gn] : 0.f;
            Bs[bRow][nn] = val;
        }
        __syncthreads();
#pragma unroll
        for (int kk = 0; kk < 16; kk++) {
            float a[4], b[4];
#pragma unroll
            for (int i = 0; i < 4; i++) a[i] = As[kk][ty * 4 + i];
#pragma unroll
            for (int i = 0; i < 4; i++) b[i] = Bs[kk][tx * 4 + i];
#pragma unroll
            for (int i = 0; i < 4; i++)
#pragma unroll
                for (int j = 0; j < 4; j++) acc[i][j] += a[i] * b[j];
        }
        __syncthreads();
    }

#pragma unroll
    for (int i = 0; i < 4; i++) {
        int gm = bm + ty * 4 + i;
        if (gm >= M) continue;
#pragma unroll
        for (int j = 0; j < 4; j++) {
            int gn = bn + tx * 4 + j;
            if (gn >= N) continue;
            float v = acc[i][j];
            if (bias) v += bias[gn];
            if (act == 1) v = v / (1.f + __expf(-v));
            else if (act == 2) v = 1.f / (1.f + __expf(-v));
            if (mulp) v *= mulp[(long)gm * ldc + gn];
            if (resp) v += resp[(long)gm * ldc + gn];
            C[(long)gm * ldc + gn] = v;
        }
    }
}

// ---------------- group norm over 64: l2norm on two buffers in one launch ----------------
__global__ void groupnorm64_pair_k(float* __restrict__ qb, float* __restrict__ kb) {
    int g = blockIdx.x * 8 + (threadIdx.x >> 5);
    int lane = threadIdx.x & 31;
    float* p = (blockIdx.y ? kb : qb) + (size_t)g * 64;
    float a = p[lane], b = p[lane + 32];
    float s = a * a + b * b;
#pragma unroll
    for (int off = 16; off; off >>= 1) s += __shfl_xor_sync(0xffffffffu, s, off);
    float r = rsqrtf(s + 1e-6f);
    p[lane] = a * r;
    p[lane + 32] = b * r;
}

// ---------------- group norm over 64 (rmsnorm*w) ----------------
__global__ void groupnorm64_k(float* __restrict__ x, const float* __restrict__ w, int mode) {
    int g = blockIdx.x * 8 + (threadIdx.x >> 5);
    int lane = threadIdx.x & 31;
    float* p = x + (size_t)g * 64;
    float a = p[lane], b = p[lane + 32];
    float s = a * a + b * b;
#pragma unroll
    for (int off = 16; off; off >>= 1) s += __shfl_xor_sync(0xffffffffu, s, off);
    float r = (mode == 0) ? rsqrtf(s + 1e-6f) : rsqrtf(s * (1.f / 64.f) + 1e-6f);
    float wa = mode ? w[lane] : 1.f;
    float wb = mode ? w[lane + 32] : 1.f;
    p[lane] = a * r * wa;
    p[lane + 32] = b * r * wb;
}

// ---------------- row rmsnorm over D ----------------
__global__ void rmsnorm_row_k(const float* __restrict__ x, const float* __restrict__ w,
                              float* __restrict__ out) {
    int t = blockIdx.x;
    const float* p = x + (size_t)t * D;
    __shared__ float red[256];
    float s = 0.f;
    for (int i = threadIdx.x; i < D; i += 256) {
        float v = p[i];
        s += v * v;
    }
    red[threadIdx.x] = s;
    __syncthreads();
    for (int off = 128; off; off >>= 1) {
        if (threadIdx.x < off) red[threadIdx.x] += red[threadIdx.x + off];
        __syncthreads();
    }
    float r = rsqrtf(red[0] * (1.f / D) + 1e-6f);
    for (int i = threadIdx.x; i < D; i += 256)
        out[(size_t)t * D + i] = p[i] * r * w[i];
}

// ---------------- WY prep: per (chunk, head) — M solve + AQK (chunk-parallel) ----------------
// M = I + B*stril(K K^T); solves M [BV | BK] -> [Utilde | W]; AQK = tril(Q K^T) inclusive.
__global__ void wy_prep_k(const float* __restrict__ q, const float* __restrict__ k,
                          const float* __restrict__ v, const float* __restrict__ beta,
                          float* __restrict__ wy_u, float* __restrict__ wy_w,
                          float* __restrict__ wy_aqk) {
    int c = blockIdx.x, h = blockIdx.y;
    int t0 = c * 64;
    extern __shared__ float sm[];
    float* sK = sm;                 // [64][65]
    float* sM = sm + 64 * 65;       // [64][65]
    float* sX = sm + 2 * 64 * 65;   // [64][130]
    int tid = threadIdx.x;
    int ty = tid >> 4, tx = tid & 15;

    for (int i = tid; i < 64 * 64; i += 256) {
        int r = i >> 6, d = i & 63;
        sK[r * 65 + d] = k[(size_t)(t0 + r) * D + h * 64 + d];
    }
    __syncthreads();

    // M entries (j < i): b_i * (k_i . k_j)
#pragma unroll
    for (int ii = 0; ii < 4; ii++) {
        int i = ty * 4 + ii;
        float bi = beta[(t0 + i) * H + h];
#pragma unroll
        for (int jj = 0; jj < 4; jj++) {
            int j = tx * 4 + jj;
            if (j < i) {
                float acc = 0.f;
                for (int d = 0; d < 64; d++) acc += sK[i * 65 + d] * sK[j * 65 + d];
                sM[i * 65 + j] = bi * acc;
            }
        }
    }
    // Q into sX (temp), then AQK = tril(QK^T)
    for (int i = tid; i < 64 * 64; i += 256) {
        int r = i >> 6, d = i & 63;
        sX[r * 130 + d] = q[(size_t)(t0 + r) * D + h * 64 + d];
    }
    __syncthreads();
    float* aqk_out = wy_aqk + ((size_t)(h * 16 + c)) * 4096;
#pragma unroll
    for (int ii = 0; ii < 4; ii++) {
        int i = ty * 4 + ii;
#pragma unroll
        for (int jj = 0; jj < 4; jj++) {
            int j = tx * 4 + jj;
            float val = 0.f;
            if (j <= i) {
                float acc = 0.f;
                for (int d = 0; d < 64; d++) acc += sX[i * 130 + d] * sK[j * 65 + d];
                val = acc;
            }
            aqk_out[i * 64 + j] = val;
        }
    }
    __syncthreads();
    // RHS: X[:, 0:64] = B V, X[:, 64:128] = B K
    for (int i = tid; i < 64 * 64; i += 256) {
        int r = i >> 6, d = i & 63;
        float bi = beta[(t0 + r) * H + h];
        sX[r * 130 + d] = bi * v[(size_t)(t0 + r) * D + h * 64 + d];
        sX[r * 130 + 64 + d] = bi * sK[r * 65 + d];
    }
    __syncthreads();
    // forward substitution — column tid is thread-private, no barriers needed
    if (tid < 128) {
        for (int i = 1; i < 64; i++) {
            float acc = sX[i * 130 + tid];
            for (int j = 0; j < i; j++) acc -= sM[i * 65 + j] * sX[j * 130 + tid];
            sX[i * 130 + tid] = acc;
        }
    }
    __syncthreads();
    float* u_out = wy_u + ((size_t)(h * 16 + c)) * 4096;
    float* w_out = wy_w + ((size_t)(h * 16 + c)) * 4096;
    for (int i = tid; i < 64 * 64; i += 256) {
        int r = i >> 6, d = i & 63;
        u_out[i] = sX[r * 130 + d];
        w_out[i] = sX[r * 130 + 64 + d];
    }
}

// ---------------- WY sequential: per (v-slice, head), 16 chunk steps ----------------
// U = Utilde - W S;  O = Q S + AQK U;  S += K^T U.   v-slice = 8 cols per block.
__global__ __launch_bounds__(256) void wy_seq_k(
        const float* __restrict__ wy_u, const float* __restrict__ wy_w,
        const float* __restrict__ wy_aqk, const float* __restrict__ q,
        const float* __restrict__ k, float* __restrict__ o) {
    int vb = blockIdx.x;  // 0..7
    int h = blockIdx.y;
    __shared__ float sOp[64 * 65];
    __shared__ float sS[64 * 10];
    __shared__ float sU[64 * 10];
    int tid = threadIdx.x;
    int row = tid & 63;
    int cp = tid >> 6;  // 0..3
    int c0 = cp * 2;

    for (int i = tid; i < 64 * 10; i += 256) sS[i] = 0.f;
    __syncthreads();

    for (int c = 0; c < 16; c++) {
        size_t base = ((size_t)(h * 16 + c)) * 4096;
        int t0 = c * 64;
        // stage W
        for (int i = tid; i < 4096; i += 256) sOp[(i >> 6) * 65 + (i & 63)] = wy_w[base + i];
        __syncthreads();
        float u0 = 0.f, u1 = 0.f;
        for (int kk = 0; kk < 64; kk++) {
            float a = sOp[row * 65 + kk];
            float2 s2 = *(const float2*)&sS[kk * 10 + c0];
            u0 += a * s2.x;
            u1 += a * s2.y;
        }
        u0 = wy_u[base + row * 64 + vb * 8 + c0] - u0;
        u1 = wy_u[base + row * 64 + vb * 8 + c0 + 1] - u1;
        __syncthreads();  // all W reads done before restaging sOp
        sU[row * 10 + c0] = u0;
        sU[row * 10 + c0 + 1] = u1;
        // stage Q
        for (int i = tid; i < 4096; i += 256)
            sOp[(i >> 6) * 65 + (i & 63)] = q[(size_t)(t0 + (i >> 6)) * D + h * 64 + (i & 63)];
        __syncthreads();
        float o0 = 0.f, o1 = 0.f;
        for (int kk = 0; kk < 64; kk++) {
            float a = sOp[row * 65 + kk];
            float2 s2 = *(const float2*)&sS[kk * 10 + c0];
            o0 += a * s2.x;
            o1 += a * s2.y;
        }
        __syncthreads();
        // stage AQK
        for (int i = tid; i < 4096; i += 256) sOp[(i >> 6) * 65 + (i & 63)] = wy_aqk[base + i];
        __syncthreads();
        for (int kk = 0; kk < 64; kk++) {
            float a = sOp[row * 65 + kk];
            float2 s2 = *(const float2*)&sU[kk * 10 + c0];
            o0 += a * s2.x;
            o1 += a * s2.y;
        }
        o[(size_t)(t0 + row) * D + h * 64 + vb * 8 + c0] = o0;
        o[(size_t)(t0 + row) * D + h * 64 + vb * 8 + c0 + 1] = o1;
        __syncthreads();
        // stage K
        for (int i = tid; i < 4096; i += 256)
            sOp[(i >> 6) * 65 + (i & 63)] = k[(size_t)(t0 + (i >> 6)) * D + h * 64 + (i & 63)];
        __syncthreads();
        float s0 = 0.f, s1 = 0.f;
        for (int i = 0; i < 64; i++) {
            float a = sOp[i * 65 + row];
            float2 u2 = *(const float2*)&sU[i * 10 + c0];
            s0 += a * u2.x;
            s1 += a * u2.y;
        }
        sS[row * 10 + c0] += s0;
        sS[row * 10 + c0 + 1] += s1;
        __syncthreads();
    }
}

// ---------------- row softmax over 1024 ----------------
__global__ void softmax_k(float* __restrict__ scores) {
    size_t row = blockIdx.x;
    float* p = scores + row * T;
    __shared__ float red[256];
    int tid = threadIdx.x;

    float v4[4];
    float m = -1e30f;
#pragma unroll
    for (int i = 0; i < 4; i++) {
        v4[i] = p[tid + i * 256];
        m = fmaxf(m, v4[i]);
    }
    red[tid] = m;
    __syncthreads();
    for (int off = 128; off; off >>= 1) {
        if (tid < off) red[tid] = fmaxf(red[tid], red[tid + off]);
        __syncthreads();
    }
    m = red[0];
    __syncthreads();

    float s = 0.f;
#pragma unroll
    for (int i = 0; i < 4; i++) {
        v4[i] = __expf(v4[i] - m);
        s += v4[i];
    }
    red[tid] = s;
    __syncthreads();
    for (int off = 128; off; off >>= 1) {
        if (tid < off) red[tid] += red[tid + off];
        __syncthreads();
    }
    float inv = 1.f / red[0];
#pragma unroll
    for (int i = 0; i < 4; i++) p[tid + i * 256] = v4[i] * inv;
}

// ---------------- host orchestration ----------------
static uint2 *s_asp, *s_bsp, *s_ktp, *s_vcp;

static void presplitA(const float* src, int nElts) {
    presplitA_k<<<(nElts / 2 + 255) / 256, 256>>>(src, s_asp, nElts / 2);
}
static void presplitB(const float* src, int K, int N) {
    presplitB_k<<<((K / 2) * N + 255) / 256, 256>>>(src, s_bsp, K, N);
}
static void presplitAB(const float* a, int nA, const float* b, int Kb, int Nb) {
    int npA = nA / 2, nB = (Kb / 2) * Nb;
    presplitAB_k<<<(npA + nB + 255) / 256, 256>>>(a, s_asp, npA, b, s_bsp, Kb, Nb);
}
static void tc_gemm(const float* bias, const float* mulb, const float* resb, float* C,
                    int M, int N, int K, int ldb, int ldc, int act,
                    int batch = 1, long sApairs = 0, long sBpairs = 0, long sC = 0,
                    int ldapairs = -1) {
    if (ldapairs < 0) ldapairs = K / 2;
    dim3 g(N / 64, M / 64, batch);
    tcgemm_k<<<g, 256>>>(s_asp, s_bsp, bias, mulb, resb, C, M, N, K / 2, ldapairs, ldb, ldc,
                         sApairs, sBpairs, sC, act, 0);
}

extern "C" void kernel_launch(void* const* d_in, const int* in_sizes, int n_in,
                              void* d_out, int out_size) {
    const int* ids = (const int*)d_in[0];
    const float* emb = (const float*)d_in[1];
    const float* enc_Wq = (const float*)d_in[2];
    const float* enc_Wk = (const float*)d_in[3];
    const float* enc_Wv = (const float*)d_in[4];
    const float* enc_Wb = (const float*)d_in[5];
    const float* enc_nw = (const float*)d_in[6];
    const float* enc_Wo = (const float*)d_in[7];
    const float* ck_W = (const float*)d_in[8];
    const float* ck_b = (const float*)d_in[9];
    const float* cv_W = (const float*)d_in[10];
    const float* cv_b = (const float*)d_in[11];
    const float* dn_Wq = (const float*)d_in[12];
    const float* dn_Wk = (const float*)d_in[13];
    const float* dn_Wv = (const float*)d_in[14];
    const float* dn_Wb = (const float*)d_in[15];
    const float* dn_nw = (const float*)d_in[16];
    const float* dn_Wo = (const float*)d_in[17];
    const float* sw_in_w = (const float*)d_in[18];
    const float* sw_post_w = (const float*)d_in[19];
    const float* sw_Wq = (const float*)d_in[20];
    const float* sw_Wo = (const float*)d_in[21];
    const float* sw_up_W = (const float*)d_in[22];
    const float* sw_up_b = (const float*)d_in[23];
    const float* sw_gate_W = (const float*)d_in[24];
    const float* sw_gate_b = (const float*)d_in[25];
    const float* sw_down_W = (const float*)d_in[26];
    const float* sw_down_b = (const float*)d_in[27];
    const float* final_w = (const float*)d_in[28];

    float *hs, *hbuf, *q, *k, *v, *beta, *o, *kc, *vc, *kcr, *scores, *ff1, *ff2, *ct, *st;
    float *wy_u, *wy_w, *wy_aqk;
    cudaGetSymbolAddress((void**)&hs, g_hs);
    cudaGetSymbolAddress((void**)&hbuf, g_hbuf);
    cudaGetSymbolAddress((void**)&q, g_q);
    cudaGetSymbolAddress((void**)&k, g_k);
    cudaGetSymbolAddress((void**)&v, g_v);
    cudaGetSymbolAddress((void**)&beta, g_beta);
    cudaGetSymbolAddress((void**)&o, g_o);
    cudaGetSymbolAddress((void**)&kc, g_kc);
    cudaGetSymbolAddress((void**)&vc, g_vc);
    cudaGetSymbolAddress((void**)&kcr, g_kcr);
    cudaGetSymbolAddress((void**)&scores, g_scores);
    cudaGetSymbolAddress((void**)&ff1, g_ff1);
    cudaGetSymbolAddress((void**)&ff2, g_ff2);
    cudaGetSymbolAddress((void**)&ct, g_cos);
    cudaGetSymbolAddress((void**)&st, g_sin);
    cudaGetSymbolAddress((void**)&s_asp, g_asp);
    cudaGetSymbolAddress((void**)&s_bsp, g_bsp);
    cudaGetSymbolAddress((void**)&s_ktp, g_ktp);
    cudaGetSymbolAddress((void**)&s_vcp, g_vcp);
    cudaGetSymbolAddress((void**)&wy_u, g_wy_u);
    cudaGetSymbolAddress((void**)&wy_w, g_wy_w);
    cudaGetSymbolAddress((void**)&wy_aqk, g_wy_aqk);

    cudaFuncSetAttribute(wy_prep_k, cudaFuncAttributeMaxDynamicSharedMemorySize, 66560);

    embed_k<<<T, 256>>>(ids, emb, hs);
    rope_tab_k<<<T, 32>>>(ct, st);

    auto deltanet = [&](const float* Wq, const float* Wk, const float* Wv, const float* Wb,
                        const float* nw, const float* Wo) {
        presplitAB(hs, T * D, Wq, D, D);
        tc_gemm(nullptr, nullptr, nullptr, q, T, D, D, D, D, 1);
        presplitB(Wk, D, D);
        tc_gemm(nullptr, nullptr, nullptr, k, T, D, D, D, D, 1);
        presplitB(Wv, D, D);
        tc_gemm(nullptr, nullptr, nullptr, v, T, D, D, D, D, 1);
        {
            dim3 g((H + 63) / 64, T / 64, 1);
            gemm_k<<<g, 256>>>(hs, Wb, nullptr, nullptr, nullptr, beta, T, H, D, D, H, H,
                               0, 0, 0, 2);
        }
        groupnorm64_pair_k<<<dim3(T * H / 8, 2), 256>>>(q, k);
        wy_prep_k<<<dim3(16, H), 256, 66560>>>(q, k, v, beta, wy_u, wy_w, wy_aqk);
        wy_seq_k<<<dim3(8, H), 256>>>(wy_u, wy_w, wy_aqk, q, k, o);
        groupnorm64_k<<<T * H / 8, 256>>>(o, nw, 1);
        presplitAB(o, T * D, Wo, D, D);
        tc_gemm(nullptr, nullptr, nullptr, hs, T, D, D, D, D, 0);
    };

    for (int l = 0; l < 4; l++)
        deltanet(enc_Wq + (long)l * D * D, enc_Wk + (long)l * D * D, enc_Wv + (long)l * D * D,
                 enc_Wb + (long)l * D * H, enc_nw + (long)l * DHD, enc_Wo + (long)l * D * D);

    presplitAB(hs, T * D, ck_W, D, D);
    tc_gemm(ck_b, nullptr, nullptr, kc, T, D, D, D, D, 0);
    presplitB(cv_W, D, D);
    tc_gemm(cv_b, nullptr, nullptr, vc, T, D, D, D, D, 0);
    rope_apply_k<<<(T * H * 32 + 255) / 256, 256>>>(kc, kcr, ct, st);

    presplitKT_k<<<dim3(T / 32, H), 256>>>(kcr, s_ktp);
    presplitB_k<<<((T / 2) * D + 255) / 256, 256>>>(vc, s_vcp, T, D);

    auto switcher = [&](int j) {
        rmsnorm_row_k<<<T, 256>>>(hs, sw_in_w + (long)j * D, hbuf);
        presplitAB(hbuf, T * D, sw_Wq + (long)j * D * D, D, D);
        tc_gemm(nullptr, nullptr, nullptr, q, T, D, D, D, D, 0);
        rope_apply_k<<<(T * H * 32 + 255) / 256, 256>>>(q, q, ct, st);
        presplitA(q, T * D);
        tcgemm_k<<<dim3(T / 64, T / 64, H), 256>>>(
            s_asp, s_ktp, nullptr, nullptr, nullptr, scores,
            T, T, 32, D / 2, H * T, T, 32, T, (long)T * T, 3, 0);
        softmax_k<<<H * T, 256>>>(scores);
        presplitA(scores, H * T * T);
        tcgemm_k<<<dim3(1, T / 64, H), 256>>>(
            s_asp, s_vcp, nullptr, nullptr, nullptr, o,
            T, DHD, T / 2, T / 2, D, D, (long)T * T / 2, 64, 64, 0, 1);
        presplitAB(o, T * D, sw_Wo + (long)j * D * D, D, D);
        tc_gemm(nullptr, nullptr, hs, hs, T, D, D, D, D, 0);
        rmsnorm_row_k<<<T, 256>>>(hs, sw_post_w + (long)j * D, hbuf);
        presplitAB(hbuf, T * D, sw_up_W + (long)j * D * DFF, D, DFF);
        tc_gemm(sw_up_b + (long)j * DFF, nullptr, nullptr, ff1, T, DFF, D, DFF, DFF, 0);
        presplitB(sw_gate_W + (long)j * D * DFF, D, DFF);
        tc_gemm(sw_gate_b + (long)j * DFF, ff1, nullptr, ff2, T, DFF, D, DFF, DFF, 2);
        presplitAB(ff2, T * DFF, sw_down_W + (long)j * DFF * D, DFF, D);
        tc_gemm(sw_down_b + (long)j * D, nullptr, hs, hs, T, D, DFF, D, D, 0);
    };

    switcher(0);
    deltanet(dn_Wq, dn_Wk, dn_Wv, dn_Wb, dn_nw, dn_Wo);
    switcher(1);
    deltanet(dn_Wq + (long)D * D, dn_Wk + (long)D * D, dn_Wv + (long)D * D,
             dn_Wb + (long)D * H, dn_nw + DHD, dn_Wo + (long)D * D);

    rmsnorm_row_k<<<T, 256>>>(hs, final_w, (float*)d_out);
}

// round 16
// speedup vs baseline: 1.1597x; 1.1597x over previous
#include <cuda_runtime.h>
#include <cuda_bf16.h>

#define T 1024
#define D 1024
#define H 16
#define DHD 64
#define DFF 4096

// ---------------- static scratch (device globals; no allocation) ----------------
__device__ float g_hs[T * D];
__device__ float g_hbuf[T * D];
__device__ float g_q[T * D];
__device__ float g_k[T * D];
__device__ float g_v[T * D];
__device__ float g_beta[T * H];
__device__ float g_o[T * D];
__device__ float g_kc[T * D];
__device__ float g_vc[T * D];
__device__ float g_kcr[T * D];
__device__ float g_scores[(size_t)H * T * T];
__device__ float g_ff1[T * DFF];
__device__ float g_ff2[T * DFF];
__device__ float g_cos[T * 32];
__device__ float g_sin[T * 32];
__device__ uint2 g_asp[(size_t)H * T * T / 2];  // pre-split A (max: scores)
__device__ uint2 g_bsp[(size_t)D * DFF / 2];    // pre-split B (max: up/gate W)
__device__ uint2 g_ktp[32 * H * T];             // pre-split K^T pairs [32][H*T]
__device__ uint2 g_vcp[(T / 2) * D];            // pre-split vc pairs [T/2][D]

// ---------------- embedding gather ----------------
__global__ void embed_k(const int* __restrict__ ids, const float* __restrict__ emb,
                        float* __restrict__ out) {
    int t = blockIdx.x;
    int id = ids[t];
    for (int i = threadIdx.x; i < D; i += 256)
        out[(size_t)t * D + i] = emb[(size_t)id * D + i];
}

// ---------------- rope tables ----------------
__global__ void rope_tab_k(float* __restrict__ ct, float* __restrict__ st) {
    int t = blockIdx.x, i = threadIdx.x;  // i in [0,32)
    float inv = __powf(10000.0f, -(float)i / 32.0f);
    float f = (float)t * inv;
    ct[t * 32 + i] = cosf(f);
    st[t * 32 + i] = sinf(f);
}

// rope apply on [T, H, 64]; in may equal out
__global__ void rope_apply_k(const float* __restrict__ in, float* __restrict__ out,
                             const float* __restrict__ ct, const float* __restrict__ st) {
    int idx = blockIdx.x * 256 + threadIdx.x;  // T*H*32 total
    if (idx >= T * H * 32) return;
    int d = idx & 31;
    int th = idx >> 5;
    int h = th & (H - 1);
    int t = th >> 4;
    float c = ct[t * 32 + d], s = st[t * 32 + d];
    const float* pi = in + (size_t)t * D + h * DHD;
    float* po = out + (size_t)t * D + h * DHD;
    float x0 = pi[d], x1 = pi[d + 32];
    po[d] = x0 * c - x1 * s;
    po[d + 32] = x1 * c + x0 * s;
}

// ---------------- bf16 RN split: pair (x0,x1) -> (hi bf16x2 [low=x0], lo bf16x2) ------------
__device__ __forceinline__ uint2 bfsplit2_rn(float x0, float x1) {
    unsigned hi;
    asm("cvt.rn.bf16x2.f32 %0, %1, %2;" : "=r"(hi) : "f"(x1), "f"(x0));
    float h0 = __uint_as_float(hi << 16);
    float h1 = __uint_as_float(hi & 0xFFFF0000u);
    unsigned lo;
    asm("cvt.rn.bf16x2.f32 %0, %1, %2;" : "=r"(lo) : "f"(x1 - h1), "f"(x0 - h0));
    return make_uint2(hi, lo);
}

// A-style pre-split: row-major [M][K], adjacent-k pairs. npairs = M*K/2.
__global__ void presplitA_k(const float* __restrict__ in, uint2* __restrict__ out, int npairs) {
    int i = blockIdx.x * 256 + threadIdx.x;
    if (i >= npairs) return;
    float2 v = ((const float2*)in)[i];
    out[i] = bfsplit2_rn(v.x, v.y);
}

// B-style pre-split: [K][N] row-major, pairs rows (2p, 2p+1). out[p*N + n].
__global__ void presplitB_k(const float* __restrict__ in, uint2* __restrict__ out,
                            int Kd, int Nd) {
    int i = blockIdx.x * 256 + threadIdx.x;
    if (i >= (Kd / 2) * Nd) return;
    int n = i % Nd, p = i / Nd;
    out[i] = bfsplit2_rn(in[(size_t)(2 * p) * Nd + n], in[(size_t)(2 * p + 1) * Nd + n]);
}

// K^T pre-split: kcr [T][H*64] -> out[p][h*T + s] = split(kcr[s][h*64+2p], kcr[s][h*64+2p+1])
__global__ void presplitKT_k(const float* __restrict__ in, uint2* __restrict__ out) {
    int h = blockIdx.y;
    int s0 = blockIdx.x * 32;
    __shared__ float sm[32][65];
    int tid = threadIdx.x;
    for (int idx = tid; idx < 32 * 64; idx += 256) {
        int rr = idx >> 6, cc = idx & 63;
        sm[rr][cc] = in[(size_t)(s0 + rr) * D + h * 64 + cc];
    }
    __syncthreads();
    for (int idx = tid; idx < 1024; idx += 256) {
        int p = idx >> 5, sp = idx & 31;
        out[(size_t)p * (H * T) + h * T + s0 + sp] = bfsplit2_rn(sm[sp][2 * p], sm[sp][2 * p + 1]);
    }
}

__device__ __forceinline__ void mma_bf16(float* d, unsigned a0, unsigned a1, unsigned a2,
                                         unsigned a3, unsigned b0, unsigned b1) {
    asm volatile(
        "mma.sync.aligned.m16n8k16.row.col.f32.bf16.bf16.f32 "
        "{%0,%1,%2,%3}, {%4,%5,%6,%7}, {%8,%9}, {%0,%1,%2,%3};"
        : "+f"(d[0]), "+f"(d[1]), "+f"(d[2]), "+f"(d[3])
        : "r"(a0), "r"(a1), "r"(a2), "r"(a3), "r"(b0), "r"(b1));
}

// ---------------- tensor-core GEMM (3xBF16, operands pre-split in global) ----------------
// C = act(A@B + bias) [*mul] [+res].  A: [M][Kp] uint2 pairs; B: [Kp][N] uint2 pairs.
// act: 0 none, 1 silu, 2 sigmoid, 3 causal-mask (*0.125 if gn<=gm else -1e30)
// kbound: bound K-loop to pairs < (bm+64)/2 (causal att@V — truncated entries exactly 0)
__global__ __launch_bounds__(256) void tcgemm_k(
        const uint2* __restrict__ A, const uint2* __restrict__ B,
        const float* __restrict__ bias, const float* __restrict__ mulb,
        const float* __restrict__ resb, float* __restrict__ C,
        int M, int N, int Kp, int ldap, int ldb, int ldc,
        long sAp, long sBp, long sC, int act, int kbound) {
    int bz = blockIdx.z;
    A += (long)bz * sAp;
    B += (long)bz * sBp;
    C += (long)bz * sC;
    const float* mulp = mulb ? mulb + (long)bz * sC : nullptr;
    const float* resp = resb ? resb + (long)bz * sC : nullptr;

    int bm = blockIdx.y * 64, bn = blockIdx.x * 64;

    int tid = threadIdx.x;
    int lane = tid & 31;
    int warp = tid >> 5;
    int wm = warp >> 2;   // 0..1 -> rows wm*32
    int wn = warp & 3;    // 0..3 -> cols wn*16
    int grp = lane >> 2;  // 0..7
    int tig = lane & 3;   // 0..3

    // fully-masked causal tile: write -1e30 and exit before any work
    if (act == 3 && bn >= bm + 64) {
#pragma unroll
        for (int mt = 0; mt < 2; mt++)
#pragma unroll
            for (int nt = 0; nt < 2; nt++)
#pragma unroll
                for (int r = 0; r < 4; r++) {
                    int gm = bm + wm * 32 + mt * 16 + grp + (r >> 1) * 8;
                    int gn = bn + wn * 16 + nt * 8 + tig * 2 + (r & 1);
                    C[(long)gm * ldc + gn] = -1e30f;
                }
        return;
    }

    if (kbound) {
        int lim = (bm + 64) / 2;
        if (lim < Kp) Kp = lim;
    }

    __shared__ uint2 Asp[64][12];
    __shared__ uint2 Bsp[64][12];

    // staging maps
    int arow = tid >> 2;              // 0..63
    int atig = tid & 3;               // kpairs atig, atig+4
    int bkp = lane >> 2;              // 0..7
    int bn0 = warp * 8 + (lane & 3);  // n and n+4

    uint2 aU0, aU1, bU0, bU1;
    auto gload = [&](int kp0) {
        const uint2* ap = A + (long)(bm + arow) * ldap + kp0;
        aU0 = ap[atig];
        aU1 = ap[atig + 4];
        const uint2* bp = B + (long)(kp0 + bkp) * ldb + bn;
        bU0 = bp[bn0];
        bU1 = bp[bn0 + 4];
    };
    auto sstore = [&]() {
        Asp[arow][atig] = aU0;
        Asp[arow][atig + 4] = aU1;
        Bsp[bn0][bkp] = bU0;
        Bsp[bn0 + 4][bkp] = bU1;
    };

    float acc[2][2][4];
#pragma unroll
    for (int i = 0; i < 2; i++)
#pragma unroll
        for (int j = 0; j < 2; j++)
#pragma unroll
            for (int r = 0; r < 4; r++) acc[i][j][r] = 0.f;

    gload(0);
    sstore();
    __syncthreads();

    for (int kp0 = 0; kp0 < Kp; kp0 += 8) {
        bool more = (kp0 + 8) < Kp;
        if (more) gload(kp0 + 8);

        uint2 aE[2][4];
#pragma unroll
        for (int mt = 0; mt < 2; mt++) {
            int m = wm * 32 + mt * 16 + grp;
            aE[mt][0] = Asp[m][tig];
            aE[mt][1] = Asp[m + 8][tig];
            aE[mt][2] = Asp[m][tig + 4];
            aE[mt][3] = Asp[m + 8][tig + 4];
        }
        uint2 bE[2][2];
#pragma unroll
        for (int nt = 0; nt < 2; nt++) {
            int n = wn * 16 + nt * 8 + grp;
            bE[nt][0] = Bsp[n][tig];
            bE[nt][1] = Bsp[n][tig + 4];
        }
#pragma unroll
        for (int mt = 0; mt < 2; mt++)
#pragma unroll
            for (int nt = 0; nt < 2; nt++) {
                float* d = acc[mt][nt];
                mma_bf16(d, aE[mt][0].x, aE[mt][1].x, aE[mt][2].x, aE[mt][3].x,
                         bE[nt][0].x, bE[nt][1].x);  // hi*hi
                mma_bf16(d, aE[mt][0].y, aE[mt][1].y, aE[mt][2].y, aE[mt][3].y,
                         bE[nt][0].x, bE[nt][1].x);  // lo*hi
                mma_bf16(d, aE[mt][0].x, aE[mt][1].x, aE[mt][2].x, aE[mt][3].x,
                         bE[nt][0].y, bE[nt][1].y);  // hi*lo
            }
        __syncthreads();
        if (more) {
            sstore();
            __syncthreads();
        }
    }

    // epilogue (m16n8 D fragment layout)
#pragma unroll
    for (int mt = 0; mt < 2; mt++)
#pragma unroll
        for (int nt = 0; nt < 2; nt++)
#pragma unroll
            for (int r = 0; r < 4; r++) {
                int gm = bm + wm * 32 + mt * 16 + grp + (r >> 1) * 8;
                int gn = bn + wn * 16 + nt * 8 + tig * 2 + (r & 1);
                float v = acc[mt][nt][r];
                if (bias) v += bias[gn];
                if (act == 1) v = v / (1.f + __expf(-v));
                else if (act == 2) v = 1.f / (1.f + __expf(-v));
                else if (act == 3) v = (gn <= gm) ? v * 0.125f : -1e30f;
                if (mulp) v *= mulp[(long)gm * ldc + gn];
                if (resp) v += resp[(long)gm * ldc + gn];
                C[(long)gm * ldc + gn] = v;
            }
}

// ---------------- SIMT GEMM fallback (small N; float inputs) ----------------
__global__ void gemm_k(const float* __restrict__ A, const float* __restrict__ Bm,
                       const float* __restrict__ bias, const float* __restrict__ mulb,
                       const float* __restrict__ resb, float* __restrict__ C,
                       int M, int N, int K, int lda, int ldb, int ldc,
                       long sA, long sB, long sC, int act) {
    int bz = blockIdx.z;
    A += (long)bz * sA;
    Bm += (long)bz * sB;
    C += (long)bz * sC;
    const float* mulp = mulb ? mulb + (long)bz * sC : nullptr;
    const float* resp = resb ? resb + (long)bz * sC : nullptr;

    int bm = blockIdx.y * 64, bn = blockIdx.x * 64;
    __shared__ float As[16][68];
    __shared__ float Bs[16][68];
    int tid = threadIdx.x;
    int ty = tid >> 4, tx = tid & 15;
    int aRow = tid >> 2;
    int aColBase = (tid & 3) * 4;
    int bRow = tid >> 4;
    int bColBase = (tid & 15) * 4;

    float acc[4][4];
#pragma unroll
    for (int i = 0; i < 4; i++)
#pragma unroll
        for (int j = 0; j < 4; j++) acc[i][j] = 0.f;

    for (int k0 = 0; k0 < K; k0 += 16) {
#pragma unroll
        for (int i = 0; i < 4; i++) {
            int kk = aColBase + i;
            int gm = bm + aRow, gk = k0 + kk;
            float val = (gm < M) ? A[(long)gm * lda + gk] : 0.f;
            As[kk][aRow] = val;
        }
#pragma unroll
        for (int i = 0; i < 4; i++) {
            int nn = bColBase + i;
            int gn = bn + nn, gk = k0 + bRow;
            float val = (gn < N) ? Bm[(long)gk * ldb + gn] : 0.f;
            Bs[bRow][nn] = val;
        }
        __syncthreads();
#pragma unroll
        for (int kk = 0; kk < 16; kk++) {
            float a[4], b[4];
#pragma unroll
            for (int i = 0; i < 4; i++) a[i] = As[kk][ty * 4 + i];
#pragma unroll
            for (int i = 0; i < 4; i++) b[i] = Bs[kk][tx * 4 + i];
#pragma unroll
            for (int i = 0; i < 4; i++)
#pragma unroll
                for (int j = 0; j < 4; j++) acc[i][j] += a[i] * b[j];
        }
        __syncthreads();
    }

#pragma unroll
    for (int i = 0; i < 4; i++) {
        int gm = bm + ty * 4 + i;
        if (gm >= M) continue;
#pragma unroll
        for (int j = 0; j < 4; j++) {
            int gn = bn + tx * 4 + j;
            if (gn >= N) continue;
            float v = acc[i][j];
            if (bias) v += bias[gn];
            if (act == 1) v = v / (1.f + __expf(-v));
            else if (act == 2) v = 1.f / (1.f + __expf(-v));
            if (mulp) v *= mulp[(long)gm * ldc + gn];
            if (resp) v += resp[(long)gm * ldc + gn];
            C[(long)gm * ldc + gn] = v;
        }
    }
}

// ---------------- group norm over 64 (l2norm or rmsnorm*w) ----------------
__global__ void groupnorm64_k(float* __restrict__ x, const float* __restrict__ w, int mode) {
    int g = blockIdx.x * 8 + (threadIdx.x >> 5);
    int lane = threadIdx.x & 31;
    float* p = x + (size_t)g * 64;
    float a = p[lane], b = p[lane + 32];
    float s = a * a + b * b;
#pragma unroll
    for (int off = 16; off; off >>= 1) s += __shfl_xor_sync(0xffffffffu, s, off);
    float r = (mode == 0) ? rsqrtf(s + 1e-6f) : rsqrtf(s * (1.f / 64.f) + 1e-6f);
    float wa = mode ? w[lane] : 1.f;
    float wb = mode ? w[lane + 32] : 1.f;
    p[lane] = a * r * wa;
    p[lane + 32] = b * r * wb;
}

// ---------------- row rmsnorm over D ----------------
__global__ void rmsnorm_row_k(const float* __restrict__ x, const float* __restrict__ w,
                              float* __restrict__ out) {
    int t = blockIdx.x;
    const float* p = x + (size_t)t * D;
    __shared__ float red[256];
    float s = 0.f;
    for (int i = threadIdx.x; i < D; i += 256) {
        float v = p[i];
        s += v * v;
    }
    red[threadIdx.x] = s;
    __syncthreads();
    for (int off = 128; off; off >>= 1) {
        if (threadIdx.x < off) red[threadIdx.x] += red[threadIdx.x + off];
        __syncthreads();
    }
    float r = rsqrtf(red[0] * (1.f / D) + 1e-6f);
    for (int i = threadIdx.x; i < D; i += 256)
        out[(size_t)t * D + i] = p[i] * r * w[i];
}

// ---------------- DeltaNet sequential scan (R3 original) ----------------
__global__ void deltanet_scan_k(const float* __restrict__ q, const float* __restrict__ k,
                                const float* __restrict__ v, const float* __restrict__ beta,
                                float* __restrict__ o) {
    int h = blockIdx.x;
    int tid = threadIdx.x;
    int j = tid >> 2;
    int r = tid & 3;
    __shared__ float sk[2][64], sq[2][64], sv[2][64], sb[2];

    float s[16];
#pragma unroll
    for (int i = 0; i < 16; i++) s[i] = 0.f;

    if (tid < 64) sk[0][tid] = k[(size_t)h * 64 + tid];
    else if (tid < 128) sq[0][tid - 64] = q[(size_t)h * 64 + (tid - 64)];
    else if (tid < 192) sv[0][tid - 128] = v[(size_t)h * 64 + (tid - 128)];
    else if (tid == 192) sb[0] = beta[h];
    __syncthreads();

    for (int t = 0; t < T; t++) {
        int cur = t & 1, nxt = cur ^ 1;
        float pre = 0.f;
        bool havePre = (t + 1 < T) && (tid <= 192);
        if (havePre) {
            int tt = t + 1;
            if (tid < 64) pre = k[(size_t)tt * D + h * 64 + tid];
            else if (tid < 128) pre = q[(size_t)tt * D + h * 64 + (tid - 64)];
            else if (tid < 192) pre = v[(size_t)tt * D + h * 64 + (tid - 128)];
            else pre = beta[tt * H + h];
        }

        float p0 = 0.f, p1 = 0.f;
#pragma unroll
        for (int i = 0; i < 16; i += 2) {
            p0 += sk[cur][r * 16 + i] * s[i];
            p1 += sk[cur][r * 16 + i + 1] * s[i + 1];
        }
        float p = p0 + p1;
        p += __shfl_xor_sync(0xffffffffu, p, 1);
        p += __shfl_xor_sync(0xffffffffu, p, 2);

        float delta = sb[cur] * (sv[cur][j] - p);

        float o0 = 0.f, o1 = 0.f;
#pragma unroll
        for (int i = 0; i < 16; i += 2) {
            s[i] += sk[cur][r * 16 + i] * delta;
            o0 += sq[cur][r * 16 + i] * s[i];
            s[i + 1] += sk[cur][r * 16 + i + 1] * delta;
            o1 += sq[cur][r * 16 + i + 1] * s[i + 1];
        }
        float oo = o0 + o1;
        oo += __shfl_xor_sync(0xffffffffu, oo, 1);
        oo += __shfl_xor_sync(0xffffffffu, oo, 2);
        if (r == 0) o[(size_t)t * D + h * 64 + j] = oo;

        if (havePre) {
            if (tid < 64) sk[nxt][tid] = pre;
            else if (tid < 128) sq[nxt][tid - 64] = pre;
            else if (tid < 192) sv[nxt][tid - 128] = pre;
            else sb[nxt] = pre;
        }
        __syncthreads();
    }
}

// ---------------- row softmax over 1024 ----------------
__global__ void softmax_k(float* __restrict__ scores) {
    size_t row = blockIdx.x;  // h*T + t
    float* p = scores + row * T;
    __shared__ float red[256];
    int tid = threadIdx.x;

    float v4[4];
    float m = -1e30f;
#pragma unroll
    for (int i = 0; i < 4; i++) {
        v4[i] = p[tid + i * 256];
        m = fmaxf(m, v4[i]);
    }
    red[tid] = m;
    __syncthreads();
    for (int off = 128; off; off >>= 1) {
        if (tid < off) red[tid] = fmaxf(red[tid], red[tid + off]);
        __syncthreads();
    }
    m = red[0];
    __syncthreads();

    float s = 0.f;
#pragma unroll
    for (int i = 0; i < 4; i++) {
        v4[i] = __expf(v4[i] - m);
        s += v4[i];
    }
    red[tid] = s;
    __syncthreads();
    for (int off = 128; off; off >>= 1) {
        if (tid < off) red[tid] += red[tid + off];
        __syncthreads();
    }
    float inv = 1.f / red[0];
#pragma unroll
    for (int i = 0; i < 4; i++) p[tid + i * 256] = v4[i] * inv;
}

// ---------------- host orchestration ----------------
static uint2 *s_asp, *s_bsp, *s_ktp, *s_vcp;

static void presplitA(const float* src, int nElts) {
    presplitA_k<<<(nElts / 2 + 255) / 256, 256>>>(src, s_asp, nElts / 2);
}
static void presplitB(const float* src, int K, int N) {
    presplitB_k<<<((K / 2) * N + 255) / 256, 256>>>(src, s_bsp, K, N);
}
// tcgemm on pre-split operands (A = s_asp, B = s_bsp). K in floats.
static void tc_gemm(const float* bias, const float* mulb, const float* resb, float* C,
                    int M, int N, int K, int ldb, int ldc, int act,
                    int batch = 1, long sApairs = 0, long sBpairs = 0, long sC = 0,
                    int ldapairs = -1) {
    if (ldapairs < 0) ldapairs = K / 2;
    dim3 g(N / 64, M / 64, batch);
    tcgemm_k<<<g, 256>>>(s_asp, s_bsp, bias, mulb, resb, C, M, N, K / 2, ldapairs, ldb, ldc,
                         sApairs, sBpairs, sC, act, 0);
}

extern "C" void kernel_launch(void* const* d_in, const int* in_sizes, int n_in,
                              void* d_out, int out_size) {
    const int* ids = (const int*)d_in[0];
    const float* emb = (const float*)d_in[1];
    const float* enc_Wq = (const float*)d_in[2];
    const float* enc_Wk = (const float*)d_in[3];
    const float* enc_Wv = (const float*)d_in[4];
    const float* enc_Wb = (const float*)d_in[5];
    const float* enc_nw = (const float*)d_in[6];
    const float* enc_Wo = (const float*)d_in[7];
    const float* ck_W = (const float*)d_in[8];
    const float* ck_b = (const float*)d_in[9];
    const float* cv_W = (const float*)d_in[10];
    const float* cv_b = (const float*)d_in[11];
    const float* dn_Wq = (const float*)d_in[12];
    const float* dn_Wk = (const float*)d_in[13];
    const float* dn_Wv = (const float*)d_in[14];
    const float* dn_Wb = (const float*)d_in[15];
    const float* dn_nw = (const float*)d_in[16];
    const float* dn_Wo = (const float*)d_in[17];
    const float* sw_in_w = (const float*)d_in[18];
    const float* sw_post_w = (const float*)d_in[19];
    const float* sw_Wq = (const float*)d_in[20];
    const float* sw_Wo = (const float*)d_in[21];
    const float* sw_up_W = (const float*)d_in[22];
    const float* sw_up_b = (const float*)d_in[23];
    const float* sw_gate_W = (const float*)d_in[24];
    const float* sw_gate_b = (const float*)d_in[25];
    const float* sw_down_W = (const float*)d_in[26];
    const float* sw_down_b = (const float*)d_in[27];
    const float* final_w = (const float*)d_in[28];

    float *hs, *hbuf, *q, *k, *v, *beta, *o, *kc, *vc, *kcr, *scores, *ff1, *ff2, *ct, *st;
    cudaGetSymbolAddress((void**)&hs, g_hs);
    cudaGetSymbolAddress((void**)&hbuf, g_hbuf);
    cudaGetSymbolAddress((void**)&q, g_q);
    cudaGetSymbolAddress((void**)&k, g_k);
    cudaGetSymbolAddress((void**)&v, g_v);
    cudaGetSymbolAddress((void**)&beta, g_beta);
    cudaGetSymbolAddress((void**)&o, g_o);
    cudaGetSymbolAddress((void**)&kc, g_kc);
    cudaGetSymbolAddress((void**)&vc, g_vc);
    cudaGetSymbolAddress((void**)&kcr, g_kcr);
    cudaGetSymbolAddress((void**)&scores, g_scores);
    cudaGetSymbolAddress((void**)&ff1, g_ff1);
    cudaGetSymbolAddress((void**)&ff2, g_ff2);
    cudaGetSymbolAddress((void**)&ct, g_cos);
    cudaGetSymbolAddress((void**)&st, g_sin);
    cudaGetSymbolAddress((void**)&s_asp, g_asp);
    cudaGetSymbolAddress((void**)&s_bsp, g_bsp);
    cudaGetSymbolAddress((void**)&s_ktp, g_ktp);
    cudaGetSymbolAddress((void**)&s_vcp, g_vcp);

    embed_k<<<T, 256>>>(ids, emb, hs);
    rope_tab_k<<<T, 32>>>(ct, st);

    auto deltanet = [&](const float* Wq, const float* Wk, const float* Wv, const float* Wb,
                        const float* nw, const float* Wo) {
        presplitA(hs, T * D);  // hs split once for q/k/v
        presplitB(Wq, D, D);
        tc_gemm(nullptr, nullptr, nullptr, q, T, D, D, D, D, 1);
        presplitB(Wk, D, D);
        tc_gemm(nullptr, nullptr, nullptr, k, T, D, D, D, D, 1);
        presplitB(Wv, D, D);
        tc_gemm(nullptr, nullptr, nullptr, v, T, D, D, D, D, 1);
        {
            dim3 g((H + 63) / 64, T / 64, 1);
            gemm_k<<<g, 256>>>(hs, Wb, nullptr, nullptr, nullptr, beta, T, H, D, D, H, H,
                               0, 0, 0, 2);
        }
        groupnorm64_k<<<T * H / 8, 256>>>(q, nullptr, 0);
        groupnorm64_k<<<T * H / 8, 256>>>(k, nullptr, 0);
        deltanet_scan_k<<<H, 256>>>(q, k, v, beta, o);
        groupnorm64_k<<<T * H / 8, 256>>>(o, nw, 1);
        presplitA(o, T * D);
        presplitB(Wo, D, D);
        tc_gemm(nullptr, nullptr, nullptr, hs, T, D, D, D, D, 0);
    };

    for (int l = 0; l < 4; l++)
        deltanet(enc_Wq + (long)l * D * D, enc_Wk + (long)l * D * D, enc_Wv + (long)l * D * D,
                 enc_Wb + (long)l * D * H, enc_nw + (long)l * DHD, enc_Wo + (long)l * D * D);

    presplitA(hs, T * D);
    presplitB(ck_W, D, D);
    tc_gemm(ck_b, nullptr, nullptr, kc, T, D, D, D, D, 0);
    presplitB(cv_W, D, D);
    tc_gemm(cv_b, nullptr, nullptr, vc, T, D, D, D, D, 0);
    rope_apply_k<<<(T * H * 32 + 255) / 256, 256>>>(kc, kcr, ct, st);

    // shared-by-both-switchers pre-splits (kcr^T per head, vc)
    presplitKT_k<<<dim3(T / 32, H), 256>>>(kcr, s_ktp);
    presplitB_k<<<((T / 2) * D + 255) / 256, 256>>>(vc, s_vcp, T, D);

    auto switcher = [&](int j) {
        rmsnorm_row_k<<<T, 256>>>(hs, sw_in_w + (long)j * D, hbuf);
        presplitA(hbuf, T * D);
        presplitB(sw_Wq + (long)j * D * D, D, D);
        tc_gemm(nullptr, nullptr, nullptr, q, T, D, D, D, D, 0);
        rope_apply_k<<<(T * H * 32 + 255) / 256, 256>>>(q, q, ct, st);
        // scores = tril(q @ k^T) / 8 on tensor cores (masked tiles exit early)
        presplitA(q, T * D);
        tcgemm_k<<<dim3(T / 64, T / 64, H), 256>>>(
            s_asp, s_ktp, nullptr, nullptr, nullptr, scores,
            T, T, 32, D / 2, H * T, T, /*sAp=*/32, /*sBp=*/T, (long)T * T, 3, 0);
        softmax_k<<<H * T, 256>>>(scores);
        // att @ V, batched over heads; kbound exploits causal zeros
        presplitA(scores, H * T * T);
        tcgemm_k<<<dim3(1, T / 64, H), 256>>>(
            s_asp, s_vcp, nullptr, nullptr, nullptr, o,
            T, DHD, T / 2, T / 2, D, D, (long)T * T / 2, 64, 64, 0, 1);
        presplitA(o, T * D);
        presplitB(sw_Wo + (long)j * D * D, D, D);
        tc_gemm(nullptr, nullptr, hs, hs, T, D, D, D, D, 0);
        rmsnorm_row_k<<<T, 256>>>(hs, sw_post_w + (long)j * D, hbuf);
        presplitA(hbuf, T * D);
        presplitB(sw_up_W + (long)j * D * DFF, D, DFF);
        tc_gemm(sw_up_b + (long)j * DFF, nullptr, nullptr, ff1, T, DFF, D, DFF, DFF, 0);
        presplitB(sw_gate_W + (long)j * D * DFF, D, DFF);
        tc_gemm(sw_gate_b + (long)j * DFF, ff1, nullptr, ff2, T, DFF, D, DFF, DFF, 2);
        presplitA(ff2, T * DFF);
        presplitB(sw_down_W + (long)j * DFF * D, DFF, D);
        tc_gemm(sw_down_b + (long)j * D, nullptr, hs, hs, T, D, DFF, D, D, 0);
    };

    switcher(0);
    deltanet(dn_Wq, dn_Wk, dn_Wv, dn_Wb, dn_nw, dn_Wo);
    switcher(1);
    deltanet(dn_Wq + (long)D * D, dn_Wk + (long)D * D, dn_Wv + (long)D * D,
             dn_Wb + (long)D * H, dn_nw + DHD, dn_Wo + (long)D * D);

    rmsnorm_row_k<<<T, 256>>>(hs, final_w, (float*)d_out);
}

// round 17
// speedup vs baseline: 1.2019x; 1.0364x over previous
#include <cuda_runtime.h>
#include <cuda_bf16.h>

#define T 1024
#define D 1024
#define H 16
#define DHD 64
#define DFF 4096

// ---------------- static scratch (device globals; no allocation) ----------------
__device__ float g_hs[T * D];
__device__ float g_hbuf[T * D];
__device__ float g_q[T * D];
__device__ float g_k[T * D];
__device__ float g_v[T * D];
__device__ float g_beta[T * H];
__device__ float g_o[T * D];
__device__ float g_kc[T * D];
__device__ float g_vc[T * D];
__device__ float g_kcr[T * D];
__device__ float g_scores[(size_t)H * T * T];
__device__ float g_ff1[T * DFF];
__device__ float g_ff2[T * DFF];
__device__ float g_cos[T * 32];
__device__ float g_sin[T * 32];
__device__ uint2 g_asp[(size_t)H * T * T / 2];  // pre-split A (max: attention weights)
__device__ uint2 g_bsp[(size_t)D * DFF / 2];    // pre-split B (max: up/gate W)
__device__ uint2 g_ktp[32 * H * T];             // pre-split K^T pairs [32][H*T]
__device__ uint2 g_vcp[(T / 2) * D];            // pre-split vc pairs [T/2][D]

// ---------------- embedding gather ----------------
__global__ void embed_k(const int* __restrict__ ids, const float* __restrict__ emb,
                        float* __restrict__ out) {
    int t = blockIdx.x;
    int id = ids[t];
    for (int i = threadIdx.x; i < D; i += 256)
        out[(size_t)t * D + i] = emb[(size_t)id * D + i];
}

// ---------------- rope tables ----------------
__global__ void rope_tab_k(float* __restrict__ ct, float* __restrict__ st) {
    int t = blockIdx.x, i = threadIdx.x;  // i in [0,32)
    float inv = __powf(10000.0f, -(float)i / 32.0f);
    float f = (float)t * inv;
    ct[t * 32 + i] = cosf(f);
    st[t * 32 + i] = sinf(f);
}

// rope apply on [T, H, 64]; in may equal out
__global__ void rope_apply_k(const float* __restrict__ in, float* __restrict__ out,
                             const float* __restrict__ ct, const float* __restrict__ st) {
    int idx = blockIdx.x * 256 + threadIdx.x;  // T*H*32 total
    if (idx >= T * H * 32) return;
    int d = idx & 31;
    int th = idx >> 5;
    int h = th & (H - 1);
    int t = th >> 4;
    float c = ct[t * 32 + d], s = st[t * 32 + d];
    const float* pi = in + (size_t)t * D + h * DHD;
    float* po = out + (size_t)t * D + h * DHD;
    float x0 = pi[d], x1 = pi[d + 32];
    po[d] = x0 * c - x1 * s;
    po[d + 32] = x1 * c + x0 * s;
}

// ---------------- bf16 RN split: pair (x0,x1) -> (hi bf16x2 [low=x0], lo bf16x2) ------------
__device__ __forceinline__ uint2 bfsplit2_rn(float x0, float x1) {
    unsigned hi;
    asm("cvt.rn.bf16x2.f32 %0, %1, %2;" : "=r"(hi) : "f"(x1), "f"(x0));
    float h0 = __uint_as_float(hi << 16);
    float h1 = __uint_as_float(hi & 0xFFFF0000u);
    unsigned lo;
    asm("cvt.rn.bf16x2.f32 %0, %1, %2;" : "=r"(lo) : "f"(x1 - h1), "f"(x0 - h0));
    return make_uint2(hi, lo);
}

// A-style pre-split: row-major [M][K], adjacent-k pairs. npairs = M*K/2.
__global__ void presplitA_k(const float* __restrict__ in, uint2* __restrict__ out, int npairs) {
    int i = blockIdx.x * 256 + threadIdx.x;
    if (i >= npairs) return;
    float2 v = ((const float2*)in)[i];
    out[i] = bfsplit2_rn(v.x, v.y);
}

// B-style pre-split: [K][N] row-major, pairs rows (2p, 2p+1). out[p*N + n].
__global__ void presplitB_k(const float* __restrict__ in, uint2* __restrict__ out,
                            int Kd, int Nd) {
    int i = blockIdx.x * 256 + threadIdx.x;
    if (i >= (Kd / 2) * Nd) return;
    int n = i % Nd, p = i / Nd;
    out[i] = bfsplit2_rn(in[(size_t)(2 * p) * Nd + n], in[(size_t)(2 * p + 1) * Nd + n]);
}

// K^T pre-split: kcr [T][H*64] -> out[p][h*T + s] = split(kcr[s][h*64+2p], kcr[s][h*64+2p+1])
__global__ void presplitKT_k(const float* __restrict__ in, uint2* __restrict__ out) {
    int h = blockIdx.y;
    int s0 = blockIdx.x * 32;
    __shared__ float sm[32][65];
    int tid = threadIdx.x;
    for (int idx = tid; idx < 32 * 64; idx += 256) {
        int rr = idx >> 6, cc = idx & 63;
        sm[rr][cc] = in[(size_t)(s0 + rr) * D + h * 64 + cc];
    }
    __syncthreads();
    for (int idx = tid; idx < 1024; idx += 256) {
        int p = idx >> 5, sp = idx & 31;
        out[(size_t)p * (H * T) + h * T + s0 + sp] = bfsplit2_rn(sm[sp][2 * p], sm[sp][2 * p + 1]);
    }
}

__device__ __forceinline__ void mma_bf16(float* d, unsigned a0, unsigned a1, unsigned a2,
                                         unsigned a3, unsigned b0, unsigned b1) {
    asm volatile(
        "mma.sync.aligned.m16n8k16.row.col.f32.bf16.bf16.f32 "
        "{%0,%1,%2,%3}, {%4,%5,%6,%7}, {%8,%9}, {%0,%1,%2,%3};"
        : "+f"(d[0]), "+f"(d[1]), "+f"(d[2]), "+f"(d[3])
        : "r"(a0), "r"(a1), "r"(a2), "r"(a3), "r"(b0), "r"(b1));
}

// ---------------- tensor-core GEMM (3xBF16, operands pre-split in global) ----------------
// C = act(A@B + bias) [*mul] [+res].  A: [M][Kp] uint2 pairs; B: [Kp][N] uint2 pairs.
// act: 0 none, 1 silu, 2 sigmoid, 3 causal-mask (*0.125 if gn<=gm; masked tiles write NOTHING)
// kbound: bound K-loop to pairs < (bm+64)/2 (causal att@V — truncated entries exactly 0)
__global__ __launch_bounds__(256) void tcgemm_k(
        const uint2* __restrict__ A, const uint2* __restrict__ B,
        const float* __restrict__ bias, const float* __restrict__ mulb,
        const float* __restrict__ resb, float* __restrict__ C,
        int M, int N, int Kp, int ldap, int ldb, int ldc,
        long sAp, long sBp, long sC, int act, int kbound) {
    int bz = blockIdx.z;
    A += (long)bz * sAp;
    B += (long)bz * sBp;
    C += (long)bz * sC;
    const float* mulp = mulb ? mulb + (long)bz * sC : nullptr;
    const float* resp = resb ? resb + (long)bz * sC : nullptr;

    int bm = blockIdx.y * 64, bn = blockIdx.x * 64;

    // fully-masked causal tile: consumer never reads it — exit without writing
    if (act == 3 && bn >= bm + 64) return;

    int tid = threadIdx.x;
    int lane = tid & 31;
    int warp = tid >> 5;
    int wm = warp >> 2;   // 0..1 -> rows wm*32
    int wn = warp & 3;    // 0..3 -> cols wn*16
    int grp = lane >> 2;  // 0..7
    int tig = lane & 3;   // 0..3

    if (kbound) {
        int lim = (bm + 64) / 2;
        if (lim < Kp) Kp = lim;
    }

    __shared__ uint2 Asp[64][12];
    __shared__ uint2 Bsp[64][12];

    // staging maps
    int arow = tid >> 2;              // 0..63
    int atig = tid & 3;               // kpairs atig, atig+4
    int bkp = lane >> 2;              // 0..7
    int bn0 = warp * 8 + (lane & 3);  // n and n+4

    uint2 aU0, aU1, bU0, bU1;
    auto gload = [&](int kp0) {
        const uint2* ap = A + (long)(bm + arow) * ldap + kp0;
        aU0 = ap[atig];
        aU1 = ap[atig + 4];
        const uint2* bp = B + (long)(kp0 + bkp) * ldb + bn;
        bU0 = bp[bn0];
        bU1 = bp[bn0 + 4];
    };
    auto sstore = [&]() {
        Asp[arow][atig] = aU0;
        Asp[arow][atig + 4] = aU1;
        Bsp[bn0][bkp] = bU0;
        Bsp[bn0 + 4][bkp] = bU1;
    };

    float acc[2][2][4];
#pragma unroll
    for (int i = 0; i < 2; i++)
#pragma unroll
        for (int j = 0; j < 2; j++)
#pragma unroll
            for (int r = 0; r < 4; r++) acc[i][j][r] = 0.f;

    gload(0);
    sstore();
    __syncthreads();

    for (int kp0 = 0; kp0 < Kp; kp0 += 8) {
        bool more = (kp0 + 8) < Kp;
        if (more) gload(kp0 + 8);

        uint2 aE[2][4];
#pragma unroll
        for (int mt = 0; mt < 2; mt++) {
            int m = wm * 32 + mt * 16 + grp;
            aE[mt][0] = Asp[m][tig];
            aE[mt][1] = Asp[m + 8][tig];
            aE[mt][2] = Asp[m][tig + 4];
            aE[mt][3] = Asp[m + 8][tig + 4];
        }
        uint2 bE[2][2];
#pragma unroll
        for (int nt = 0; nt < 2; nt++) {
            int n = wn * 16 + nt * 8 + grp;
            bE[nt][0] = Bsp[n][tig];
            bE[nt][1] = Bsp[n][tig + 4];
        }
#pragma unroll
        for (int mt = 0; mt < 2; mt++)
#pragma unroll
            for (int nt = 0; nt < 2; nt++) {
                float* d = acc[mt][nt];
                mma_bf16(d, aE[mt][0].x, aE[mt][1].x, aE[mt][2].x, aE[mt][3].x,
                         bE[nt][0].x, bE[nt][1].x);  // hi*hi
                mma_bf16(d, aE[mt][0].y, aE[mt][1].y, aE[mt][2].y, aE[mt][3].y,
                         bE[nt][0].x, bE[nt][1].x);  // lo*hi
                mma_bf16(d, aE[mt][0].x, aE[mt][1].x, aE[mt][2].x, aE[mt][3].x,
                         bE[nt][0].y, bE[nt][1].y);  // hi*lo
            }
        __syncthreads();
        if (more) {
            sstore();
            __syncthreads();
        }
    }

    // epilogue (m16n8 D fragment layout)
#pragma unroll
    for (int mt = 0; mt < 2; mt++)
#pragma unroll
        for (int nt = 0; nt < 2; nt++)
#pragma unroll
            for (int r = 0; r < 4; r++) {
                int gm = bm + wm * 32 + mt * 16 + grp + (r >> 1) * 8;
                int gn = bn + wn * 16 + nt * 8 + tig * 2 + (r & 1);
                float v = acc[mt][nt][r];
                if (bias) v += bias[gn];
                if (act == 1) v = v / (1.f + __expf(-v));
                else if (act == 2) v = 1.f / (1.f + __expf(-v));
                else if (act == 3) v = (gn <= gm) ? v * 0.125f : -1e30f;
                if (mulp) v *= mulp[(long)gm * ldc + gn];
                if (resp) v += resp[(long)gm * ldc + gn];
                C[(long)gm * ldc + gn] = v;
            }
}

// ---------------- SIMT GEMM fallback (small N; float inputs) ----------------
__global__ void gemm_k(const float* __restrict__ A, const float* __restrict__ Bm,
                       const float* __restrict__ bias, const float* __restrict__ mulb,
                       const float* __restrict__ resb, float* __restrict__ C,
                       int M, int N, int K, int lda, int ldb, int ldc,
                       long sA, long sB, long sC, int act) {
    int bz = blockIdx.z;
    A += (long)bz * sA;
    Bm += (long)bz * sB;
    C += (long)bz * sC;
    const float* mulp = mulb ? mulb + (long)bz * sC : nullptr;
    const float* resp = resb ? resb + (long)bz * sC : nullptr;

    int bm = blockIdx.y * 64, bn = blockIdx.x * 64;
    __shared__ float As[16][68];
    __shared__ float Bs[16][68];
    int tid = threadIdx.x;
    int ty = tid >> 4, tx = tid & 15;
    int aRow = tid >> 2;
    int aColBase = (tid & 3) * 4;
    int bRow = tid >> 4;
    int bColBase = (tid & 15) * 4;

    float acc[4][4];
#pragma unroll
    for (int i = 0; i < 4; i++)
#pragma unroll
        for (int j = 0; j < 4; j++) acc[i][j] = 0.f;

    for (int k0 = 0; k0 < K; k0 += 16) {
#pragma unroll
        for (int i = 0; i < 4; i++) {
            int kk = aColBase + i;
            int gm = bm + aRow, gk = k0 + kk;
            float val = (gm < M) ? A[(long)gm * lda + gk] : 0.f;
            As[kk][aRow] = val;
        }
#pragma unroll
        for (int i = 0; i < 4; i++) {
            int nn = bColBase + i;
            int gn = bn + nn, gk = k0 + bRow;
            float val = (gn < N) ? Bm[(long)gk * ldb + gn] : 0.f;
            Bs[bRow][nn] = val;
        }
        __syncthreads();
#pragma unroll
        for (int kk = 0; kk < 16; kk++) {
            float a[4], b[4];
#pragma unroll
            for (int i = 0; i < 4; i++) a[i] = As[kk][ty * 4 + i];
#pragma unroll
            for (int i = 0; i < 4; i++) b[i] = Bs[kk][tx * 4 + i];
#pragma unroll
            for (int i = 0; i < 4; i++)
#pragma unroll
                for (int j = 0; j < 4; j++) acc[i][j] += a[i] * b[j];
        }
        __syncthreads();
    }

#pragma unroll
    for (int i = 0; i < 4; i++) {
        int gm = bm + ty * 4 + i;
        if (gm >= M) continue;
#pragma unroll
        for (int j = 0; j < 4; j++) {
            int gn = bn + tx * 4 + j;
            if (gn >= N) continue;
            float v = acc[i][j];
            if (bias) v += bias[gn];
            if (act == 1) v = v / (1.f + __expf(-v));
            else if (act == 2) v = 1.f / (1.f + __expf(-v));
            if (mulp) v *= mulp[(long)gm * ldc + gn];
            if (resp) v += resp[(long)gm * ldc + gn];
            C[(long)gm * ldc + gn] = v;
        }
    }
}

// ---------------- group norm over 64 (l2norm or rmsnorm*w) ----------------
__global__ void groupnorm64_k(float* __restrict__ x, const float* __restrict__ w, int mode) {
    int g = blockIdx.x * 8 + (threadIdx.x >> 5);
    int lane = threadIdx.x & 31;
    float* p = x + (size_t)g * 64;
    float a = p[lane], b = p[lane + 32];
    float s = a * a + b * b;
#pragma unroll
    for (int off = 16; off; off >>= 1) s += __shfl_xor_sync(0xffffffffu, s, off);
    float r = (mode == 0) ? rsqrtf(s + 1e-6f) : rsqrtf(s * (1.f / 64.f) + 1e-6f);
    float wa = mode ? w[lane] : 1.f;
    float wb = mode ? w[lane + 32] : 1.f;
    p[lane] = a * r * wa;
    p[lane + 32] = b * r * wb;
}

// ---------------- row rmsnorm over D ----------------
__global__ void rmsnorm_row_k(const float* __restrict__ x, const float* __restrict__ w,
                              float* __restrict__ out) {
    int t = blockIdx.x;
    const float* p = x + (size_t)t * D;
    __shared__ float red[256];
    float s = 0.f;
    for (int i = threadIdx.x; i < D; i += 256) {
        float v = p[i];
        s += v * v;
    }
    red[threadIdx.x] = s;
    __syncthreads();
    for (int off = 128; off; off >>= 1) {
        if (threadIdx.x < off) red[threadIdx.x] += red[threadIdx.x + off];
        __syncthreads();
    }
    float r = rsqrtf(red[0] * (1.f / D) + 1e-6f);
    for (int i = threadIdx.x; i < D; i += 256)
        out[(size_t)t * D + i] = p[i] * r * w[i];
}

// ---------------- DeltaNet sequential scan (R3 original) ----------------
__global__ void deltanet_scan_k(const float* __restrict__ q, const float* __restrict__ k,
                                const float* __restrict__ v, const float* __restrict__ beta,
                                float* __restrict__ o) {
    int h = blockIdx.x;
    int tid = threadIdx.x;
    int j = tid >> 2;
    int r = tid & 3;
    __shared__ float sk[2][64], sq[2][64], sv[2][64], sb[2];

    float s[16];
#pragma unroll
    for (int i = 0; i < 16; i++) s[i] = 0.f;

    if (tid < 64) sk[0][tid] = k[(size_t)h * 64 + tid];
    else if (tid < 128) sq[0][tid - 64] = q[(size_t)h * 64 + (tid - 64)];
    else if (tid < 192) sv[0][tid - 128] = v[(size_t)h * 64 + (tid - 128)];
    else if (tid == 192) sb[0] = beta[h];
    __syncthreads();

    for (int t = 0; t < T; t++) {
        int cur = t & 1, nxt = cur ^ 1;
        float pre = 0.f;
        bool havePre = (t + 1 < T) && (tid <= 192);
        if (havePre) {
            int tt = t + 1;
            if (tid < 64) pre = k[(size_t)tt * D + h * 64 + tid];
            else if (tid < 128) pre = q[(size_t)tt * D + h * 64 + (tid - 64)];
            else if (tid < 192) pre = v[(size_t)tt * D + h * 64 + (tid - 128)];
            else pre = beta[tt * H + h];
        }

        float p0 = 0.f, p1 = 0.f;
#pragma unroll
        for (int i = 0; i < 16; i += 2) {
            p0 += sk[cur][r * 16 + i] * s[i];
            p1 += sk[cur][r * 16 + i + 1] * s[i + 1];
        }
        float p = p0 + p1;
        p += __shfl_xor_sync(0xffffffffu, p, 1);
        p += __shfl_xor_sync(0xffffffffu, p, 2);

        float delta = sb[cur] * (sv[cur][j] - p);

        float o0 = 0.f, o1 = 0.f;
#pragma unroll
        for (int i = 0; i < 16; i += 2) {
            s[i] += sk[cur][r * 16 + i] * delta;
            o0 += sq[cur][r * 16 + i] * s[i];
            s[i + 1] += sk[cur][r * 16 + i + 1] * delta;
            o1 += sq[cur][r * 16 + i + 1] * s[i + 1];
        }
        float oo = o0 + o1;
        oo += __shfl_xor_sync(0xffffffffu, oo, 1);
        oo += __shfl_xor_sync(0xffffffffu, oo, 2);
        if (r == 0) o[(size_t)t * D + h * 64 + j] = oo;

        if (havePre) {
            if (tid < 64) sk[nxt][tid] = pre;
            else if (tid < 128) sq[nxt][tid - 64] = pre;
            else if (tid < 192) sv[nxt][tid - 128] = pre;
            else sb[nxt] = pre;
        }
        __syncthreads();
    }
}

// ---------------- fused causal softmax + bf16 split -> attention-weight pairs -------------
// One block per (t, h). Reads scores[h][t][0..t], softmax, writes uint2 pairs into asp
// (A-layout, ldap = T/2, batch stride T*T/2) for pairs < pend; entries beyond t are exact 0.
// pend = tile bound consumed by the kbound att@V GEMM.
__global__ __launch_bounds__(256) void softmax_split_k(const float* __restrict__ scores,
                                                       uint2* __restrict__ asp) {
    int t = blockIdx.x, h = blockIdx.y;
    size_t row = (size_t)h * T + t;
    const float* p = scores + row * T;
    __shared__ float ex[T];
    __shared__ float red[256];
    int tid = threadIdx.x;
    int nv = t + 1;

    float m = -1e30f;
    for (int i = tid; i < nv; i += 256) m = fmaxf(m, p[i]);
    red[tid] = m;
    __syncthreads();
    for (int off = 128; off; off >>= 1) {
        if (tid < off) red[tid] = fmaxf(red[tid], red[tid + off]);
        __syncthreads();
    }
    m = red[0];
    __syncthreads();

    float s = 0.f;
    for (int i = tid; i < nv; i += 256) {
        float e = __expf(p[i] - m);
        ex[i] = e;
        s += e;
    }
    red[tid] = s;
    __syncthreads();
    for (int off = 128; off; off >>= 1) {
        if (tid < off) red[tid] += red[tid + off];
        __syncthreads();
    }
    float inv = 1.f / red[0];
    __syncthreads();

    int pend = ((t >> 6) + 1) * 32;  // pairs covering s < roundup(t+1, 64)
    uint2* out = asp + row * (T / 2);
    for (int pi = tid; pi < pend; pi += 256) {
        int s0 = 2 * pi, s1 = 2 * pi + 1;
        float x0 = (s0 < nv) ? ex[s0] * inv : 0.f;
        float x1 = (s1 < nv) ? ex[s1] * inv : 0.f;
        out[pi] = bfsplit2_rn(x0, x1);
    }
}

// ---------------- host orchestration ----------------
static uint2 *s_asp, *s_bsp, *s_ktp, *s_vcp;

static void presplitA(const float* src, int nElts) {
    presplitA_k<<<(nElts / 2 + 255) / 256, 256>>>(src, s_asp, nElts / 2);
}
static void presplitB(const float* src, int K, int N) {
    presplitB_k<<<((K / 2) * N + 255) / 256, 256>>>(src, s_bsp, K, N);
}
// tcgemm on pre-split operands (A = s_asp, B = s_bsp). K in floats.
static void tc_gemm(const float* bias, const float* mulb, const float* resb, float* C,
                    int M, int N, int K, int ldb, int ldc, int act,
                    int batch = 1, long sApairs = 0, long sBpairs = 0, long sC = 0,
                    int ldapairs = -1) {
    if (ldapairs < 0) ldapairs = K / 2;
    dim3 g(N / 64, M / 64, batch);
    tcgemm_k<<<g, 256>>>(s_asp, s_bsp, bias, mulb, resb, C, M, N, K / 2, ldapairs, ldb, ldc,
                         sApairs, sBpairs, sC, act, 0);
}

extern "C" void kernel_launch(void* const* d_in, const int* in_sizes, int n_in,
                              void* d_out, int out_size) {
    const int* ids = (const int*)d_in[0];
    const float* emb = (const float*)d_in[1];
    const float* enc_Wq = (const float*)d_in[2];
    const float* enc_Wk = (const float*)d_in[3];
    const float* enc_Wv = (const float*)d_in[4];
    const float* enc_Wb = (const float*)d_in[5];
    const float* enc_nw = (const float*)d_in[6];
    const float* enc_Wo = (const float*)d_in[7];
    const float* ck_W = (const float*)d_in[8];
    const float* ck_b = (const float*)d_in[9];
    const float* cv_W = (const float*)d_in[10];
    const float* cv_b = (const float*)d_in[11];
    const float* dn_Wq = (const float*)d_in[12];
    const float* dn_Wk = (const float*)d_in[13];
    const float* dn_Wv = (const float*)d_in[14];
    const float* dn_Wb = (const float*)d_in[15];
    const float* dn_nw = (const float*)d_in[16];
    const float* dn_Wo = (const float*)d_in[17];
    const float* sw_in_w = (const float*)d_in[18];
    const float* sw_post_w = (const float*)d_in[19];
    const float* sw_Wq = (const float*)d_in[20];
    const float* sw_Wo = (const float*)d_in[21];
    const float* sw_up_W = (const float*)d_in[22];
    const float* sw_up_b = (const float*)d_in[23];
    const float* sw_gate_W = (const float*)d_in[24];
    const float* sw_gate_b = (const float*)d_in[25];
    const float* sw_down_W = (const float*)d_in[26];
    const float* sw_down_b = (const float*)d_in[27];
    const float* final_w = (const float*)d_in[28];

    float *hs, *hbuf, *q, *k, *v, *beta, *o, *kc, *vc, *kcr, *scores, *ff1, *ff2, *ct, *st;
    cudaGetSymbolAddress((void**)&hs, g_hs);
    cudaGetSymbolAddress((void**)&hbuf, g_hbuf);
    cudaGetSymbolAddress((void**)&q, g_q);
    cudaGetSymbolAddress((void**)&k, g_k);
    cudaGetSymbolAddress((void**)&v, g_v);
    cudaGetSymbolAddress((void**)&beta, g_beta);
    cudaGetSymbolAddress((void**)&o, g_o);
    cudaGetSymbolAddress((void**)&kc, g_kc);
    cudaGetSymbolAddress((void**)&vc, g_vc);
    cudaGetSymbolAddress((void**)&kcr, g_kcr);
    cudaGetSymbolAddress((void**)&scores, g_scores);
    cudaGetSymbolAddress((void**)&ff1, g_ff1);
    cudaGetSymbolAddress((void**)&ff2, g_ff2);
    cudaGetSymbolAddress((void**)&ct, g_cos);
    cudaGetSymbolAddress((void**)&st, g_sin);
    cudaGetSymbolAddress((void**)&s_asp, g_asp);
    cudaGetSymbolAddress((void**)&s_bsp, g_bsp);
    cudaGetSymbolAddress((void**)&s_ktp, g_ktp);
    cudaGetSymbolAddress((void**)&s_vcp, g_vcp);

    embed_k<<<T, 256>>>(ids, emb, hs);
    rope_tab_k<<<T, 32>>>(ct, st);

    auto deltanet = [&](const float* Wq, const float* Wk, const float* Wv, const float* Wb,
                        const float* nw, const float* Wo) {
        presplitA(hs, T * D);  // hs split once for q/k/v
        presplitB(Wq, D, D);
        tc_gemm(nullptr, nullptr, nullptr, q, T, D, D, D, D, 1);
        presplitB(Wk, D, D);
        tc_gemm(nullptr, nullptr, nullptr, k, T, D, D, D, D, 1);
        presplitB(Wv, D, D);
        tc_gemm(nullptr, nullptr, nullptr, v, T, D, D, D, D, 1);
        {
            dim3 g((H + 63) / 64, T / 64, 1);
            gemm_k<<<g, 256>>>(hs, Wb, nullptr, nullptr, nullptr, beta, T, H, D, D, H, H,
                               0, 0, 0, 2);
        }
        groupnorm64_k<<<T * H / 8, 256>>>(q, nullptr, 0);
        groupnorm64_k<<<T * H / 8, 256>>>(k, nullptr, 0);
        deltanet_scan_k<<<H, 256>>>(q, k, v, beta, o);
        groupnorm64_k<<<T * H / 8, 256>>>(o, nw, 1);
        presplitA(o, T * D);
        presplitB(Wo, D, D);
        tc_gemm(nullptr, nullptr, nullptr, hs, T, D, D, D, D, 0);
    };

    for (int l = 0; l < 4; l++)
        deltanet(enc_Wq + (long)l * D * D, enc_Wk + (long)l * D * D, enc_Wv + (long)l * D * D,
                 enc_Wb + (long)l * D * H, enc_nw + (long)l * DHD, enc_Wo + (long)l * D * D);

    presplitA(hs, T * D);
    presplitB(ck_W, D, D);
    tc_gemm(ck_b, nullptr, nullptr, kc, T, D, D, D, D, 0);
    presplitB(cv_W, D, D);
    tc_gemm(cv_b, nullptr, nullptr, vc, T, D, D, D, D, 0);
    rope_apply_k<<<(T * H * 32 + 255) / 256, 256>>>(kc, kcr, ct, st);

    // shared-by-both-switchers pre-splits (kcr^T per head, vc)
    presplitKT_k<<<dim3(T / 32, H), 256>>>(kcr, s_ktp);
    presplitB_k<<<((T / 2) * D + 255) / 256, 256>>>(vc, s_vcp, T, D);

    auto switcher = [&](int j) {
        rmsnorm_row_k<<<T, 256>>>(hs, sw_in_w + (long)j * D, hbuf);
        presplitA(hbuf, T * D);
        presplitB(sw_Wq + (long)j * D * D, D, D);
        tc_gemm(nullptr, nullptr, nullptr, q, T, D, D, D, D, 0);
        rope_apply_k<<<(T * H * 32 + 255) / 256, 256>>>(q, q, ct, st);
        // scores = tril(q @ k^T) / 8 on tensor cores (masked tiles write nothing)
        presplitA(q, T * D);
        tcgemm_k<<<dim3(T / 64, T / 64, H), 256>>>(
            s_asp, s_ktp, nullptr, nullptr, nullptr, scores,
            T, T, 32, D / 2, H * T, T, /*sAp=*/32, /*sBp=*/T, (long)T * T, 3, 0);
        // fused causal softmax + split directly into asp pairs
        softmax_split_k<<<dim3(T, H), 256>>>(scores, s_asp);
        // att @ V, batched over heads; kbound matches the pairs written above
        tcgemm_k<<<dim3(1, T / 64, H), 256>>>(
            s_asp, s_vcp, nullptr, nullptr, nullptr, o,
            T, DHD, T / 2, T / 2, D, D, (long)T * T / 2, 64, 64, 0, 1);
        presplitA(o, T * D);
        presplitB(sw_Wo + (long)j * D * D, D, D);
        tc_gemm(nullptr, nullptr, hs, hs, T, D, D, D, D, 0);
        rmsnorm_row_k<<<T, 256>>>(hs, sw_post_w + (long)j * D, hbuf);
        presplitA(hbuf, T * D);
        presplitB(sw_up_W + (long)j * D * DFF, D, DFF);
        tc_gemm(sw_up_b + (long)j * DFF, nullptr, nullptr, ff1, T, DFF, D, DFF, DFF, 0);
        presplitB(sw_gate_W + (long)j * D * DFF, D, DFF);
        tc_gemm(sw_gate_b + (long)j * DFF, ff1, nullptr, ff2, T, DFF, D, DFF, DFF, 2);
        presplitA(ff2, T * DFF);
        presplitB(sw_down_W + (long)j * DFF * D, DFF, D);
        tc_gemm(sw_down_b + (long)j * D, nullptr, hs, hs, T, D, DFF, D, D, 0);
    };

    switcher(0);
    deltanet(dn_Wq, dn_Wk, dn_Wv, dn_Wb, dn_nw, dn_Wo);
    switcher(1);
    deltanet(dn_Wq + (long)D * D, dn_Wk + (long)D * D, dn_Wv + (long)D * D,
             dn_Wb + (long)D * H, dn_nw + DHD, dn_Wo + (long)D * D);

    rmsnorm_row_k<<<T, 256>>>(hs, final_w, (float*)d_out);
}